// round 4
// baseline (speedup 1.0000x reference)
#include <cuda_runtime.h>

#define NB 256
#define NS 512
#define NI 3
#define NH 512
#define NO 3

typedef unsigned long long u64;

__device__ __forceinline__ u64 pack2(float lo, float hi) {
    u64 r; asm("mov.b64 %0, {%1, %2};" : "=l"(r) : "f"(lo), "f"(hi)); return r;
}
__device__ __forceinline__ void unpack2(u64 v, float& lo, float& hi) {
    asm("mov.b64 {%0, %1}, %2;" : "=f"(lo), "=f"(hi) : "l"(v));
}
__device__ __forceinline__ u64 fma2(u64 a, u64 b, u64 c) {
    u64 d; asm("fma.rn.f32x2 %0, %1, %2, %3;" : "=l"(d) : "l"(a), "l"(b), "l"(c)); return d;
}
__device__ __forceinline__ u64 mul2(u64 a, u64 b) {
    u64 d; asm("mul.rn.f32x2 %0, %1, %2;" : "=l"(d) : "l"(a), "l"(b)); return d;
}
__device__ __forceinline__ u64 add2(u64 a, u64 b) {
    u64 d; asm("add.rn.f32x2 %0, %1, %2;" : "=l"(d) : "l"(a), "l"(b)); return d;
}
__device__ __forceinline__ float rcpf(float a) {
    float r; asm("rcp.approx.f32 %0, %1;" : "=f"(r) : "f"(a)); return r;
}
__device__ __forceinline__ float hadd2(u64 v) {
    float lo, hi; unpack2(v, lo, hi); return lo + hi;
}

// One warp per batch; 2 warps/CTA x 128 CTAs = one warp per SMSP on 128 SMs.
// Each lane owns 16 h-indices as 8 packed f32x2 pairs (elements 2j,2j+1 of its
// four float4-groups at h = k*128 + lane*4). All per-element math runs on the
// packed fma.rn.f32x2 pipe; only rcp (MUFU) and the cross-lane butterflies are
// scalar. r_out is stored as st.global.v2.b64 (128-bit) straight from packed regs.
__global__ __launch_bounds__(64, 1)
void lr_rnn_kernel(const float* __restrict__ x, const float* __restrict__ Um,
                   const float* __restrict__ Vm, const float* __restrict__ Wi,
                   const float* __restrict__ bi, const float* __restrict__ Wo,
                   const float* __restrict__ bo, float* __restrict__ out)
{
    const int warp = threadIdx.x >> 5;
    const int lane = threadIdx.x & 31;
    const int b = blockIdx.x * 2 + warp;

    float* __restrict__ out_y = out;                               // [B,S,O]
    float* __restrict__ out_h = out + (size_t)NB * NS * NO;        // [B,H]
    float* __restrict__ out_r = out_h + (size_t)NB * NH;           // [B,S,H]

    // Packed weight pairs: index j in 0..7, elements (k=j>>1)*128+lane*4+(j&1)*2 {+0,+1}.
    u64 U0[8], U1[8], V0[8], V1[8], WI0[8], WI1[8], WI2[8], BI[8], WO0[8], WO1[8], WO2[8];

#pragma unroll
    for (int k = 0; k < 4; k++) {
        const int base = k * 128 + lane * 4;
        float4 t;
        t = *(const float4*)(Um + base);        U0[2*k] = pack2(t.x, t.y); U0[2*k+1] = pack2(t.z, t.w);
        t = *(const float4*)(Um + NH + base);   U1[2*k] = pack2(t.x, t.y); U1[2*k+1] = pack2(t.z, t.w);
        t = *(const float4*)(Vm + base);        V0[2*k] = pack2(t.x, t.y); V0[2*k+1] = pack2(t.z, t.w);
        t = *(const float4*)(Vm + NH + base);   V1[2*k] = pack2(t.x, t.y); V1[2*k+1] = pack2(t.z, t.w);
        t = *(const float4*)(bi + base);        BI[2*k] = pack2(t.x, t.y); BI[2*k+1] = pack2(t.z, t.w);
        t = *(const float4*)(Wo + base);        WO0[2*k] = pack2(t.x, t.y); WO0[2*k+1] = pack2(t.z, t.w);
        t = *(const float4*)(Wo + NH + base);   WO1[2*k] = pack2(t.x, t.y); WO1[2*k+1] = pack2(t.z, t.w);
        t = *(const float4*)(Wo + 2*NH + base); WO2[2*k] = pack2(t.x, t.y); WO2[2*k+1] = pack2(t.z, t.w);
#pragma unroll
        for (int h = 0; h < 2; h++) {
            const int e = base + h * 2;
            WI0[2*k+h] = pack2(Wi[e * NI + 0], Wi[(e + 1) * NI + 0]);
            WI1[2*k+h] = pack2(Wi[e * NI + 1], Wi[(e + 1) * NI + 1]);
            WI2[2*k+h] = pack2(Wi[e * NI + 2], Wi[(e + 1) * NI + 2]);
        }
    }
    const float bo_l = (lane < NO) ? bo[lane] : 0.0f;

    // Pade [7/6] tanh coefficients, packed.
    const u64 ONE2 = pack2(1.0f, 1.0f);
    const u64 CN3 = pack2(7.399565e-6f, 7.399565e-6f);
    const u64 CN2 = pack2(2.797202797e-3f, 2.797202797e-3f);
    const u64 CN1 = pack2(1.282051282e-1f, 1.282051282e-1f);
    const u64 CD3 = pack2(2.0720e-4f, 2.0720e-4f);
    const u64 CD2 = pack2(2.331002331e-2f, 2.331002331e-2f);
    const u64 CD1 = pack2(4.615384615e-1f, 4.615384615e-1f);

    const float* __restrict__ xb = x + (size_t)b * NS * NI;
    float* __restrict__ rb = out_r + (size_t)b * NS * NH;
    float* __restrict__ yb = out_y + (size_t)b * NS * NO;

    float p0 = 0.0f, p1 = 0.0f;
    u64 T[8];

    float xs0 = xb[0], xs1 = xb[1], xs2 = xb[2];

    for (int s = 0; s < NS; s++) {
        const int sn = (s + 1 < NS) ? (s + 1) : (NS - 1);
        const float nx0 = __ldg(xb + sn * 3 + 0);
        const float nx1 = __ldg(xb + sn * 3 + 1);
        const float nx2 = __ldg(xb + sn * 3 + 2);

        const u64 X0 = pack2(xs0, xs0);
        const u64 X1 = pack2(xs1, xs1);
        const u64 X2 = pack2(xs2, xs2);
        const u64 P0 = pack2(p0, p0);
        const u64 P1 = pack2(p1, p1);

        u64 aP0 = 0ull, aP1 = 0ull, aO0 = 0ull, aO1 = 0ull, aO2 = 0ull;

#pragma unroll
        for (int j = 0; j < 8; j++) {
            u64 z = fma2(WI0[j], X0, BI[j]);
            z = fma2(WI1[j], X1, z);
            z = fma2(WI2[j], X2, z);
            z = fma2(U0[j], P0, z);
            z = fma2(U1[j], P1, z);

            const u64 w = mul2(z, z);
            u64 N = fma2(w, CN3, CN2);
            N = fma2(w, N, CN1);
            N = fma2(w, N, ONE2);
            u64 D = fma2(w, CD3, CD2);
            D = fma2(w, D, CD1);
            D = fma2(w, D, ONE2);
            const u64 zN = mul2(z, N);
            float dx, dy; unpack2(D, dx, dy);
            const u64 t = mul2(zN, pack2(rcpf(dx), rcpf(dy)));
            T[j] = t;

            aP0 = fma2(V0[j], t, aP0);
            aP1 = fma2(V1[j], t, aP1);
            aO0 = fma2(WO0[j], t, aO0);
            aO1 = fma2(WO1[j], t, aO1);
            aO2 = fma2(WO2[j], t, aO2);
        }

        float np0 = hadd2(aP0);
        float np1 = hadd2(aP1);
        float o0  = hadd2(aO0);
        float o1  = hadd2(aO1);
        float o2  = hadd2(aO2);

        // p first: it gates step s+1.
#pragma unroll
        for (int off = 16; off; off >>= 1) {
            np0 += __shfl_xor_sync(0xffffffffu, np0, off);
            np1 += __shfl_xor_sync(0xffffffffu, np1, off);
        }
        p0 = np0; p1 = np1;

#pragma unroll
        for (int off = 16; off; off >>= 1) {
            o0 += __shfl_xor_sync(0xffffffffu, o0, off);
            o1 += __shfl_xor_sync(0xffffffffu, o1, off);
            o2 += __shfl_xor_sync(0xffffffffu, o2, off);
        }

        // r_out[b, s, :] — 128-bit stores straight from packed regs.
        float* rs = rb + (size_t)s * NH;
#pragma unroll
        for (int k = 0; k < 4; k++)
            asm volatile("st.global.v2.b64 [%0], {%1, %2};"
                         :: "l"(rs + k * 128 + lane * 4), "l"(T[2*k]), "l"(T[2*k+1])
                         : "memory");

        if (lane < NO) {
            const float ov = (lane == 0) ? o0 : ((lane == 1) ? o1 : o2);
            yb[s * NO + lane] = ov + bo_l;
        }

        xs0 = nx0; xs1 = nx1; xs2 = nx2;
    }

    // h_last[b, :]
#pragma unroll
    for (int k = 0; k < 4; k++)
        asm volatile("st.global.v2.b64 [%0], {%1, %2};"
                     :: "l"(out_h + (size_t)b * NH + k * 128 + lane * 4),
                        "l"(T[2*k]), "l"(T[2*k+1])
                     : "memory");
}

extern "C" void kernel_launch(void* const* d_in, const int* in_sizes, int n_in,
                              void* d_out, int out_size)
{
    const float* x  = (const float*)d_in[0];
    const float* U  = (const float*)d_in[1];
    const float* V  = (const float*)d_in[2];
    const float* Wi = (const float*)d_in[3];
    const float* bi = (const float*)d_in[4];
    const float* Wo = (const float*)d_in[5];
    const float* bo = (const float*)d_in[6];

    lr_rnn_kernel<<<128, 64>>>(x, U, V, Wi, bi, Wo, bo, (float*)d_out);
}